// round 5
// baseline (speedup 1.0000x reference)
#include <cuda_runtime.h>
#include <cuda_bf16.h>
#include <math.h>

#define NN    50000
#define DIMF  128
#define NH    8
#define HD    16
#define EE    800000
#define NRELC 2000
#define TT    200000
#define RRULE 50000
#define BB    10000
#define NPB   16
#define TV_INV 0.029462782549439483f   // 1/(3*sqrt(128))

// ---------------- device scratch (static, no runtime allocation) -------------
__device__ __align__(16) float d_x[2 * NN * DIMF];
__device__ __align__(16) float d_h[2 * NN * DIMF];
__device__ float               d_asrc[2 * NN * NH];
__device__ float               d_adst[2 * NN * NH];
__device__ __align__(16) float d_feat[2 * NN * DIMF];
__device__ __align__(16) __nv_bfloat16 d_gnorm[2 * NN * DIMF];
__device__ __align__(16) __nv_bfloat16 d_rnorm[2 * NRELC * DIMF];
__device__ int d_cnt[2 * NN];
__device__ int d_off[2 * (NN + 1)];
__device__ int d_cur[2 * NN];
__device__ int d_csrc[2 * EE];

// ---------------- f32x2 packed helpers ---------------------------------------
__device__ __forceinline__ unsigned long long pack2(float x, float y) {
    unsigned long long r;
    asm("mov.b64 %0, {%1, %2};" : "=l"(r) : "f"(x), "f"(y));
    return r;
}
__device__ __forceinline__ void unpack2(unsigned long long v, float& x, float& y) {
    asm("mov.b64 {%0, %1}, %2;" : "=f"(x), "=f"(y) : "l"(v));
}
__device__ __forceinline__ unsigned long long fma2(unsigned long long a,
                                                   unsigned long long b,
                                                   unsigned long long c) {
    unsigned long long r;
    asm("fma.rn.f32x2 %0, %1, %2, %3;" : "=l"(r) : "l"(a), "l"(b), "l"(c));
    return r;
}

// pack 4 floats -> uint2 of bf16
__device__ __forceinline__ uint2 pack_bf16x4(float a, float b, float c, float d) {
    __nv_bfloat162 p0 = __floats2bfloat162_rn(a, b);
    __nv_bfloat162 p1 = __floats2bfloat162_rn(c, d);
    uint2 u;
    u.x = *reinterpret_cast<unsigned int*>(&p0);
    u.y = *reinterpret_cast<unsigned int*>(&p1);
    return u;
}

// ---------------- CSR build (batched over both graphs) -----------------------
__global__ void k_zero_cnt() {
    int i = blockIdx.x * blockDim.x + threadIdx.x;
    if (i < 2 * NN) d_cnt[i] = 0;
}
// 4 edges per thread: 4 independent atomic chains (ATOMG lat ~318cyc)
__global__ void k_hist(const int* __restrict__ dst0, const int* __restrict__ dst1) {
    int i = (blockIdx.x * blockDim.x + threadIdx.x) * 4;
    if (i >= EE) return;
    int g = blockIdx.y;
    const int* dst = g ? dst1 : dst0;
    int4 d4 = *reinterpret_cast<const int4*>(dst + i);
    int* cnt = d_cnt + g * NN;
    atomicAdd(&cnt[d4.x], 1);
    atomicAdd(&cnt[d4.y], 1);
    atomicAdd(&cnt[d4.z], 1);
    atomicAdd(&cnt[d4.w], 1);
}
__global__ void __launch_bounds__(1024) k_scan() {
    int g = blockIdx.x;
    int t = threadIdx.x;
    int lane = t & 31, wid = t >> 5;
    __shared__ int wsum[32];
    int run = 0;
    const int NCH = (NN + 1023) / 1024;
    for (int c = 0; c < NCH; c++) {
        int i = c * 1024 + t;
        int val = (i < NN) ? d_cnt[g * NN + i] : 0;
        int incl = val;
#pragma unroll
        for (int o = 1; o < 32; o <<= 1) {
            int u = __shfl_up_sync(0xffffffffu, incl, o);
            if (lane >= o) incl += u;
        }
        if (lane == 31) wsum[wid] = incl;
        __syncthreads();
        if (wid == 0) {
            int ws = wsum[lane];
#pragma unroll
            for (int o = 1; o < 32; o <<= 1) {
                int u = __shfl_up_sync(0xffffffffu, ws, o);
                if (lane >= o) ws += u;
            }
            wsum[lane] = ws;
        }
        __syncthreads();
        int wb = (wid > 0) ? wsum[wid - 1] : 0;
        int excl = run + wb + incl - val;
        if (i < NN) {
            d_off[g * (NN + 1) + i] = excl;
            d_cur[g * NN + i] = excl;
        }
        run += wsum[31];
        __syncthreads();
    }
    if (t == 0) d_off[g * (NN + 1) + NN] = EE;
}
// 4 edges per thread: 4 independent atomic-return chains
__global__ void k_scatter(const int* __restrict__ e0, const int* __restrict__ e1) {
    int i = (blockIdx.x * blockDim.x + threadIdx.x) * 4;
    if (i >= EE) return;
    int g = blockIdx.y;
    const int* edg = g ? e1 : e0;
    int4 s4 = *reinterpret_cast<const int4*>(edg + i);
    int4 d4 = *reinterpret_cast<const int4*>(edg + EE + i);
    int* cur = d_cur + g * NN;
    int* csrc = d_csrc + (size_t)g * EE;
    int p0 = atomicAdd(&cur[d4.x], 1);
    int p1 = atomicAdd(&cur[d4.y], 1);
    int p2 = atomicAdd(&cur[d4.z], 1);
    int p3 = atomicAdd(&cur[d4.w], 1);
    csrc[p0] = s4.x;
    csrc[p1] = s4.y;
    csrc[p2] = s4.z;
    csrc[p3] = s4.w;
}

// ---- GEMM: h = x @ W, 16 nodes per block, f32x2 packed accumulation ----
__global__ void __launch_bounds__(128) k_gemm16(const float* __restrict__ x0,
                                                const float* __restrict__ x1,
                                                const float* __restrict__ W,
                                                int layer0) {
    __shared__ __align__(16) float xst[DIMF][NPB];   // transposed: [d][node]
    int g = blockIdx.y;
    const float* xsrc = layer0 ? (g ? x1 : x0) : (d_x + (size_t)g * NN * DIMF);
    int nb = blockIdx.x * NPB;
    int t = threadIdx.x;

    for (int k = t; k < NPB * DIMF; k += 128) {
        int u = k >> 7, d = k & 127;
        xst[d][u] = xsrc[(size_t)(nb + u) * DIMF + d];
    }
    __syncthreads();

    unsigned long long a[NPB / 2];
#pragma unroll
    for (int q = 0; q < NPB / 2; q++) a[q] = 0ull;

#pragma unroll 4
    for (int d = 0; d < DIMF; d++) {
        float w = __ldg(W + d * DIMF + t);
        unsigned long long w2 = pack2(w, w);
        const ulonglong2* xr = reinterpret_cast<const ulonglong2*>(&xst[d][0]);
#pragma unroll
        for (int q = 0; q < NPB / 4; q++) {
            ulonglong2 p = xr[q];
            a[2 * q]     = fma2(p.x, w2, a[2 * q]);
            a[2 * q + 1] = fma2(p.y, w2, a[2 * q + 1]);
        }
    }
    float v[NPB];
#pragma unroll
    for (int q = 0; q < NPB / 2; q++) unpack2(a[q], v[2 * q], v[2 * q + 1]);
    float* hb = d_h + (size_t)g * NN * DIMF;
#pragma unroll
    for (int u = 0; u < NPB; u++)
        hb[(size_t)(nb + u) * DIMF + t] = v[u];
}

// ---- attention scalars: warp per node ----
__global__ void __launch_bounds__(256) k_alpha(const float* __restrict__ a_s,
                                               const float* __restrict__ a_d) {
    int gt = blockIdx.x * blockDim.x + threadIdx.x;
    int n = gt >> 5, lane = gt & 31;
    if (n >= NN) return;
    int g = blockIdx.y;
    const float* hb = d_h + (size_t)g * NN * DIMF;
    float4 h4 = reinterpret_cast<const float4*>(hb + (size_t)n * DIMF)[lane];
    float4 as = reinterpret_cast<const float4*>(a_s)[lane];
    float4 ad = reinterpret_cast<const float4*>(a_d)[lane];
    float v1 = h4.x * as.x + h4.y * as.y + h4.z * as.z + h4.w * as.w;
    float v2 = h4.x * ad.x + h4.y * ad.y + h4.z * ad.z + h4.w * ad.w;
    v1 += __shfl_down_sync(0xffffffffu, v1, 2, 4);
    v2 += __shfl_down_sync(0xffffffffu, v2, 2, 4);
    v1 += __shfl_down_sync(0xffffffffu, v1, 1, 4);
    v2 += __shfl_down_sync(0xffffffffu, v2, 1, 4);
    if ((lane & 3) == 0) {
        int head = lane >> 2;
        d_asrc[(size_t)g * NN * NH + n * NH + head] = v1;
        d_adst[(size_t)g * NN * NH + n * NH + head] = v2;
    }
}

// ---- fused softmax-aggregate: warp per dst node, single pass, no atomics ----
__global__ void __launch_bounds__(256) k_agg(int last) {
    int gt = blockIdx.x * blockDim.x + threadIdx.x;
    int n = gt >> 5, lane = gt & 31;
    if (n >= NN) return;
    int g = blockIdx.y;
    const int* off = d_off + g * (NN + 1);
    const int* csrc = d_csrc + (size_t)g * EE;
    const float* hb = d_h + (size_t)g * NN * DIMF;
    const float* asb = d_asrc + (size_t)g * NN * NH;
    int head = lane >> 2;

    float adst_l = d_adst[(size_t)g * NN * NH + n * NH + head];

    int beg = off[n], end = off[n + 1];
    float4 acc = make_float4(0.f, 0.f, 0.f, 0.f);
    float den = 0.0f;

    int j = beg;
    // 4-edge unrolled main loop: maximize independent L2 loads in flight
    for (; j + 4 <= end; j += 4) {
        int s0 = __ldg(&csrc[j]);
        int s1 = __ldg(&csrc[j + 1]);
        int s2 = __ldg(&csrc[j + 2]);
        int s3 = __ldg(&csrc[j + 3]);
        float al0 = __ldg(&asb[s0 * NH + head]);
        float al1 = __ldg(&asb[s1 * NH + head]);
        float al2 = __ldg(&asb[s2 * NH + head]);
        float al3 = __ldg(&asb[s3 * NH + head]);
        float4 h0 = reinterpret_cast<const float4*>(hb + (size_t)s0 * DIMF)[lane];
        float4 h1 = reinterpret_cast<const float4*>(hb + (size_t)s1 * DIMF)[lane];
        float4 h2 = reinterpret_cast<const float4*>(hb + (size_t)s2 * DIMF)[lane];
        float4 h3 = reinterpret_cast<const float4*>(hb + (size_t)s3 * DIMF)[lane];
        float v0 = al0 + adst_l; v0 = fmaxf(v0, 0.2f * v0);
        float v1 = al1 + adst_l; v1 = fmaxf(v1, 0.2f * v1);
        float v2 = al2 + adst_l; v2 = fmaxf(v2, 0.2f * v2);
        float v3 = al3 + adst_l; v3 = fmaxf(v3, 0.2f * v3);
        float w0 = __expf(v0);
        float w1 = __expf(v1);
        float w2 = __expf(v2);
        float w3 = __expf(v3);
        den += (w0 + w1) + (w2 + w3);
        acc.x = fmaf(w0, h0.x, fmaf(w1, h1.x, fmaf(w2, h2.x, fmaf(w3, h3.x, acc.x))));
        acc.y = fmaf(w0, h0.y, fmaf(w1, h1.y, fmaf(w2, h2.y, fmaf(w3, h3.y, acc.y))));
        acc.z = fmaf(w0, h0.z, fmaf(w1, h1.z, fmaf(w2, h2.z, fmaf(w3, h3.z, acc.z))));
        acc.w = fmaf(w0, h0.w, fmaf(w1, h1.w, fmaf(w2, h2.w, fmaf(w3, h3.w, acc.w))));
    }
    for (; j < end; j++) {
        int s0 = __ldg(&csrc[j]);
        float al0 = __ldg(&asb[s0 * NH + head]);
        float4 h0 = reinterpret_cast<const float4*>(hb + (size_t)s0 * DIMF)[lane];
        float v0 = al0 + adst_l; v0 = fmaxf(v0, 0.2f * v0);
        float w0 = __expf(v0);
        den += w0;
        acc.x = fmaf(w0, h0.x, acc.x);
        acc.y = fmaf(w0, h0.y, acc.y);
        acc.z = fmaf(w0, h0.z, acc.z);
        acc.w = fmaf(w0, h0.w, acc.w);
    }

    float inv = 1.0f / fmaxf(den, 1e-16f);
    acc.x *= inv; acc.y *= inv; acc.z *= inv; acc.w *= inv;

    if (last) {
        reinterpret_cast<float4*>(d_feat + (size_t)g * NN * DIMF +
                                  (size_t)n * DIMF)[lane] = acc;
        float s2 = acc.x * acc.x + acc.y * acc.y + acc.z * acc.z + acc.w * acc.w;
#pragma unroll
        for (int o = 16; o > 0; o >>= 1) s2 += __shfl_xor_sync(0xffffffffu, s2, o);
        float sc = 1.0f / fmaxf(sqrtf(s2), 1e-12f);
        uint2 bv = pack_bf16x4(acc.x * sc, acc.y * sc, acc.z * sc, acc.w * sc);
        reinterpret_cast<uint2*>(d_gnorm + (size_t)g * NN * DIMF +
                                 (size_t)n * DIMF)[lane] = bv;
    } else {
        acc.x = (acc.x > 0.f) ? acc.x : expm1f(acc.x);
        acc.y = (acc.y > 0.f) ? acc.y : expm1f(acc.y);
        acc.z = (acc.z > 0.f) ? acc.z : expm1f(acc.z);
        acc.w = (acc.w > 0.f) ? acc.w : expm1f(acc.w);
        reinterpret_cast<float4*>(d_x + (size_t)g * NN * DIMF +
                                  (size_t)n * DIMF)[lane] = acc;
    }
}

__global__ void k_norm_rel(const float* __restrict__ rel0,
                           const float* __restrict__ rel1) {
    int gt = blockIdx.x * blockDim.x + threadIdx.x;
    int row = gt >> 5, lane = gt & 31;
    if (row >= NRELC) return;
    int g = blockIdx.y;
    const float* rel = g ? rel1 : rel0;
    float4 v = reinterpret_cast<const float4*>(rel + (size_t)row * DIMF)[lane];
    float s = v.x * v.x + v.y * v.y + v.z * v.z + v.w * v.w;
#pragma unroll
    for (int o = 16; o > 0; o >>= 1) s += __shfl_xor_sync(0xffffffffu, s, o);
    float sc = 1.0f / fmaxf(sqrtf(s), 1e-12f);
    uint2 bv = pack_bf16x4(v.x * sc, v.y * sc, v.z * sc, v.w * sc);
    reinterpret_cast<uint2*>(d_rnorm + (size_t)g * NRELC * DIMF +
                             (size_t)row * DIMF)[lane] = bv;
}

// tv over bf16-stored rows: lane loads 4 bf16 (8B) per row
__device__ __forceinline__ float transe_tv_warp(const __nv_bfloat16* gn,
                                                const __nv_bfloat16* rn,
                                                int hh, int tt, int rr, int lane) {
    uint2 au = reinterpret_cast<const uint2*>(gn + (size_t)hh * DIMF)[lane];
    uint2 bu = reinterpret_cast<const uint2*>(rn + (size_t)rr * DIMF)[lane];
    uint2 cu = reinterpret_cast<const uint2*>(gn + (size_t)tt * DIMF)[lane];
    float2 a0 = __bfloat1622float2(*reinterpret_cast<__nv_bfloat162*>(&au.x));
    float2 a1 = __bfloat1622float2(*reinterpret_cast<__nv_bfloat162*>(&au.y));
    float2 b0 = __bfloat1622float2(*reinterpret_cast<__nv_bfloat162*>(&bu.x));
    float2 b1 = __bfloat1622float2(*reinterpret_cast<__nv_bfloat162*>(&bu.y));
    float2 c0 = __bfloat1622float2(*reinterpret_cast<__nv_bfloat162*>(&cu.x));
    float2 c1 = __bfloat1622float2(*reinterpret_cast<__nv_bfloat162*>(&cu.y));
    float s = fabsf(a0.x + b0.x - c0.x) + fabsf(a0.y + b0.y - c0.y) +
              fabsf(a1.x + b1.x - c1.x) + fabsf(a1.y + b1.y - c1.y);
#pragma unroll
    for (int o = 16; o > 0; o >>= 1) s += __shfl_down_sync(0xffffffffu, s, o);
    return 1.0f - s * TV_INV;
}

__global__ void __launch_bounds__(256) k_transe(const int* __restrict__ h0,
                                                const int* __restrict__ h1,
                                                const int* __restrict__ t0,
                                                const int* __restrict__ t1,
                                                const int* __restrict__ r0,
                                                const int* __restrict__ r1,
                                                float* __restrict__ out) {
    int gt = blockIdx.x * blockDim.x + threadIdx.x;
    int w = gt >> 5, lane = gt & 31;
    if (w >= 2 * TT) return;
    int g = blockIdx.y;
    const int* hI = g ? h1 : h0;
    const int* tI = g ? t1 : t0;
    const int* rI = g ? r1 : r0;
    const __nv_bfloat16* gn = d_gnorm + (size_t)g * NN * DIMF;
    const __nv_bfloat16* rn = d_rnorm + (size_t)g * NRELC * DIMF;
    float tv = transe_tv_warp(gn, rn, hI[w], tI[w], rI[w], lane);
    if (lane == 0) out[(size_t)g * 2 * TT + w] = tv;
}

__global__ void __launch_bounds__(256) k_rule(const int* __restrict__ rh0,
                                              const int* __restrict__ rh1,
                                              const int* __restrict__ rt0,
                                              const int* __restrict__ rt1,
                                              const int* __restrict__ rr0,
                                              const int* __restrict__ rr1,
                                              const int* __restrict__ pm0,
                                              const int* __restrict__ pm1,
                                              const float* __restrict__ tvbase,
                                              float* __restrict__ out) {
    int gt = blockIdx.x * blockDim.x + threadIdx.x;
    int w = gt >> 5, lane = gt & 31;
    if (w >= RRULE) return;
    int g = blockIdx.y;
    const int* rh = g ? rh1 : rh0;
    const int* rt = g ? rt1 : rt0;
    const int* rr = g ? rr1 : rr0;
    const int* prem = g ? pm1 : pm0;
    const __nv_bfloat16* gn = d_gnorm + (size_t)g * NN * DIMF;
    const __nv_bfloat16* rn = d_rnorm + (size_t)g * NRELC * DIMF;
    const float* tv = tvbase + (size_t)g * 2 * TT;
    float rs = transe_tv_warp(gn, rn, rh[w], rt[w], rr[w], lane);
    if (lane == 0) {
        int p0 = prem[w * 2 + 0];
        int p1 = prem[w * 2 + 1];
        float f1 = (p0 < TT) ? tv[p0 * 2 + g] : 1.0f;
        float f2 = (p1 < TT) ? tv[p1 * 2 + g] : 1.0f;
        out[(size_t)g * RRULE + w] = 1.0f + f1 * f2 * (rs - 1.0f);
    }
}

__global__ void k_gather(const int* __restrict__ i0, const int* __restrict__ i1,
                         float* __restrict__ out) {
    int i = blockIdx.x * blockDim.x + threadIdx.x;
    if (i >= BB * DIMF) return;
    int g = blockIdx.y;
    const int* idx = g ? i1 : i0;
    int b = i >> 7, c = i & 127;
    out[(size_t)g * BB * DIMF + i] =
        d_feat[(size_t)g * NN * DIMF + (size_t)idx[b] * DIMF + c];
}

// ---------------- host orchestration ----------------------------------------
static inline int nblk(long n, int t) { return (int)((n + t - 1) / t); }

extern "C" void kernel_launch(void* const* d_in, const int* in_sizes, int n_in,
                              void* d_out, int out_size) {
    const float* ent0 = (const float*)d_in[0];
    const float* ent1 = (const float*)d_in[1];
    const float* rel0 = (const float*)d_in[2];
    const float* rel1 = (const float*)d_in[3];
    const float* W    = (const float*)d_in[4];
    const float* a_s  = (const float*)d_in[5];
    const float* a_d  = (const float*)d_in[6];
    const int* dat0 = (const int*)d_in[7];
    const int* dat1 = (const int*)d_in[8];
    const int* edg0 = (const int*)d_in[9];
    const int* edg1 = (const int*)d_in[10];
    const int* h0 = (const int*)d_in[11];
    const int* t0 = (const int*)d_in[12];
    const int* r0 = (const int*)d_in[13];
    const int* h1 = (const int*)d_in[14];
    const int* t1 = (const int*)d_in[15];
    const int* r1 = (const int*)d_in[16];
    const int* rh0 = (const int*)d_in[17];
    const int* rt0 = (const int*)d_in[18];
    const int* rr0 = (const int*)d_in[19];
    const int* pm0 = (const int*)d_in[20];
    const int* rh1 = (const int*)d_in[21];
    const int* rt1 = (const int*)d_in[22];
    const int* rr1 = (const int*)d_in[23];
    const int* pm1 = (const int*)d_in[24];

    float* out      = (float*)d_out;
    float* out_feat = out;
    float* out_tv   = out + 2 * (size_t)BB * DIMF;
    float* out_rule = out_tv + 4 * (size_t)TT;

    dim3 g2;

    k_zero_cnt<<<nblk(2 * NN, 256), 256>>>();
    g2 = dim3(nblk(EE / 4, 256), 2);
    k_hist<<<g2, 256>>>(edg0 + EE, edg1 + EE);
    k_scan<<<2, 1024>>>();
    k_scatter<<<g2, 256>>>(edg0, edg1);

    for (int l = 0; l < 2; l++) {
        g2 = dim3(NN / NPB, 2);
        k_gemm16<<<g2, 128>>>(ent0, ent1, W + (size_t)l * DIMF * DIMF, l == 0);
        g2 = dim3(nblk((long)NN * 32, 256), 2);
        k_alpha<<<g2, 256>>>(a_s + (size_t)l * DIMF, a_d + (size_t)l * DIMF);
        k_agg<<<g2, 256>>>(l == 1 ? 1 : 0);
    }

    g2 = dim3(nblk((long)NRELC * 32, 256), 2);
    k_norm_rel<<<g2, 256>>>(rel0, rel1);

    g2 = dim3(nblk((long)2 * TT * 32, 256), 2);
    k_transe<<<g2, 256>>>(h0, h1, t0, t1, r0, r1, out_tv);

    g2 = dim3(nblk((long)RRULE * 32, 256), 2);
    k_rule<<<g2, 256>>>(rh0, rh1, rt0, rt1, rr0, rr1, pm0, pm1, out_tv, out_rule);

    g2 = dim3(nblk((long)BB * DIMF, 256), 2);
    k_gather<<<g2, 256>>>(dat0, dat1, out_feat);

    (void)in_sizes; (void)n_in; (void)out_size;
}

// round 6
// speedup vs baseline: 1.0141x; 1.0141x over previous
#include <cuda_runtime.h>
#include <cuda_bf16.h>
#include <math.h>

#define NN    50000
#define DIMF  128
#define NH    8
#define EE    800000
#define NRELC 2000
#define TT    200000
#define RRULE 50000
#define BB    10000
#define TV_INV 0.029462782549439483f   // 1/(3*sqrt(128))

// gemm tiling: 8 groups of 128 threads, 8 nodes per group -> 64 nodes/block
#define GNPB   8
#define GGRP   8
#define GNODES (GNPB * GGRP)
#define GB     ((NN + GNODES - 1) / GNODES)       // 782 gemm blocks per graph
#define ZB     ((2 * NN + 1023) / 1024)           // 98
#define RB     ((2 * NRELC + 31) / 32)            // 125
#define HB     ((2 * EE + 1023) / 1024)           // 1563
#define AB     ((2 * NN + 31) / 32)               // 3125

// ---------------- device scratch ---------------------------------------------
__device__ __align__(16) float d_x[2 * NN * DIMF];
__device__ __align__(16) float d_h[2 * NN * DIMF];
__device__ float               d_asrc[2 * NN * NH];
__device__ float               d_adst[2 * NN * NH];
__device__ __align__(16) float d_feat[2 * NN * DIMF];
__device__ __align__(16) __nv_bfloat16 d_gnorm[2 * NN * DIMF];
__device__ __align__(16) __nv_bfloat16 d_rnorm[2 * NRELC * DIMF];
__device__ int d_cnt[2 * NN];
__device__ int d_off[2 * (NN + 1)];
__device__ int d_cur[2 * NN];
__device__ int d_csrc[2 * EE];

// ---------------- packed helpers ----------------------------------------------
__device__ __forceinline__ unsigned long long pack2(float x, float y) {
    unsigned long long r;
    asm("mov.b64 %0, {%1, %2};" : "=l"(r) : "f"(x), "f"(y));
    return r;
}
__device__ __forceinline__ void unpack2(unsigned long long v, float& x, float& y) {
    asm("mov.b64 {%0, %1}, %2;" : "=f"(x), "=f"(y) : "l"(v));
}
__device__ __forceinline__ unsigned long long fma2(unsigned long long a,
                                                   unsigned long long b,
                                                   unsigned long long c) {
    unsigned long long r;
    asm("fma.rn.f32x2 %0, %1, %2, %3;" : "=l"(r) : "l"(a), "l"(b), "l"(c));
    return r;
}
__device__ __forceinline__ uint2 pack_bf16x4(float a, float b, float c, float d) {
    __nv_bfloat162 p0 = __floats2bfloat162_rn(a, b);
    __nv_bfloat162 p1 = __floats2bfloat162_rn(c, d);
    uint2 u;
    u.x = *reinterpret_cast<unsigned int*>(&p0);
    u.y = *reinterpret_cast<unsigned int*>(&p1);
    return u;
}

// ================== device building blocks =====================================

__device__ __forceinline__ void dev_zero(int b) {
    int i = b * 1024 + threadIdx.x;
    if (i < 2 * NN) d_cnt[i] = 0;
}

__device__ __forceinline__ void dev_normrel(int b, const float* __restrict__ rel0,
                                            const float* __restrict__ rel1) {
    int wid = threadIdx.x >> 5, lane = threadIdx.x & 31;
    int row = b * 32 + wid;
    if (row >= 2 * NRELC) return;
    int g = row >= NRELC;
    int r = row - g * NRELC;
    const float* rel = g ? rel1 : rel0;
    float4 v = reinterpret_cast<const float4*>(rel + (size_t)r * DIMF)[lane];
    float s = v.x * v.x + v.y * v.y + v.z * v.z + v.w * v.w;
#pragma unroll
    for (int o = 16; o > 0; o >>= 1) s += __shfl_xor_sync(0xffffffffu, s, o);
    float sc = 1.0f / fmaxf(sqrtf(s), 1e-12f);
    uint2 bv = pack_bf16x4(v.x * sc, v.y * sc, v.z * sc, v.w * sc);
    reinterpret_cast<uint2*>(d_rnorm + (size_t)g * NRELC * DIMF +
                             (size_t)r * DIMF)[lane] = bv;
}

__device__ __forceinline__ void dev_hist(int b, const int* __restrict__ e0,
                                         const int* __restrict__ e1) {
    int idx = b * 1024 + threadIdx.x;
    if (idx >= 2 * EE) return;
    int g = idx >= EE;
    int e = idx - g * EE;
    const int* edg = g ? e1 : e0;
    atomicAdd(&d_cnt[g * NN + edg[EE + e]], 1);
}

__device__ __forceinline__ void dev_scatter(int b, const int* __restrict__ e0,
                                            const int* __restrict__ e1) {
    int idx = b * 1024 + threadIdx.x;
    if (idx >= 2 * EE) return;
    int g = idx >= EE;
    int e = idx - g * EE;
    const int* edg = g ? e1 : e0;
    int s = edg[e];
    int d = edg[EE + e];
    int p = atomicAdd(&d_cur[g * NN + d], 1);
    d_csrc[(size_t)g * EE + p] = s;
}

// block-wide prefix scan of d_cnt[g] -> d_off/d_cur, prefetched chunk loop
__device__ __forceinline__ void dev_scan(int* wsum, int g) {
    int t = threadIdx.x;
    int lane = t & 31, wid = t >> 5;
    const int NCH = (NN + 1023) / 1024;
    int run = 0;
    int val = (t < NN) ? d_cnt[g * NN + t] : 0;
    for (int c = 0; c < NCH; c++) {
        int inext = (c + 1) * 1024 + t;
        int vnext = (c + 1 < NCH && inext < NN) ? d_cnt[g * NN + inext] : 0;
        int incl = val;
#pragma unroll
        for (int o = 1; o < 32; o <<= 1) {
            int u = __shfl_up_sync(0xffffffffu, incl, o);
            if (lane >= o) incl += u;
        }
        if (lane == 31) wsum[wid] = incl;
        __syncthreads();
        if (wid == 0) {
            int ws = wsum[lane];
#pragma unroll
            for (int o = 1; o < 32; o <<= 1) {
                int u = __shfl_up_sync(0xffffffffu, ws, o);
                if (lane >= o) ws += u;
            }
            wsum[lane] = ws;
        }
        __syncthreads();
        int wb = (wid > 0) ? wsum[wid - 1] : 0;
        int i = c * 1024 + t;
        int excl = run + wb + incl - val;
        if (i < NN) {
            d_off[g * (NN + 1) + i] = excl;
            d_cur[g * NN + i] = excl;
        }
        run += wsum[31];
        __syncthreads();
        val = vnext;
    }
    if (t == 0) d_off[g * (NN + 1) + NN] = EE;
}

// gemm block: 8 groups x 128 threads, each group does 8 nodes
__device__ __forceinline__ void dev_gemm_block(float* smem, int nodeblk, int g,
                                               const float* __restrict__ xsrc,
                                               const float* __restrict__ W) {
    int t = threadIdx.x;
    int grp = t >> 7, lt = t & 127;
    float* xst = smem + grp * (DIMF * GNPB);   // [d][u]: d*8+u
    int nb = nodeblk * GNODES + grp * GNPB;

    for (int k = lt; k < GNPB * DIMF; k += 128) {
        int u = k >> 7, d = k & 127;
        int n = nb + u;
        xst[d * GNPB + u] = (n < NN) ? xsrc[(size_t)n * DIMF + d] : 0.0f;
    }
    __syncthreads();

    unsigned long long a0 = 0, a1 = 0, a2 = 0, a3 = 0;
#pragma unroll 4
    for (int d = 0; d < DIMF; d++) {
        float w = __ldg(W + d * DIMF + lt);
        unsigned long long w2 = pack2(w, w);
        const ulonglong2* xr = reinterpret_cast<const ulonglong2*>(xst + d * GNPB);
        ulonglong2 p0 = xr[0];
        ulonglong2 p1 = xr[1];
        a0 = fma2(p0.x, w2, a0);
        a1 = fma2(p0.y, w2, a1);
        a2 = fma2(p1.x, w2, a2);
        a3 = fma2(p1.y, w2, a3);
    }
    float v[GNPB];
    unpack2(a0, v[0], v[1]);
    unpack2(a1, v[2], v[3]);
    unpack2(a2, v[4], v[5]);
    unpack2(a3, v[6], v[7]);
    float* hb = d_h + (size_t)g * NN * DIMF;
#pragma unroll
    for (int u = 0; u < GNPB; u++) {
        int n = nb + u;
        if (n < NN) hb[(size_t)n * DIMF + lt] = v[u];
    }
}

// warp per node, flattened over both graphs
__device__ __forceinline__ void dev_alpha(int b, const float* __restrict__ a_s,
                                          const float* __restrict__ a_d) {
    int wid = threadIdx.x >> 5, lane = threadIdx.x & 31;
    int nf = b * 32 + wid;
    if (nf >= 2 * NN) return;
    int g = nf >= NN;
    int n = nf - g * NN;
    const float* hb = d_h + (size_t)g * NN * DIMF;
    float4 h4 = reinterpret_cast<const float4*>(hb + (size_t)n * DIMF)[lane];
    float4 as = reinterpret_cast<const float4*>(a_s)[lane];
    float4 ad = reinterpret_cast<const float4*>(a_d)[lane];
    float v1 = h4.x * as.x + h4.y * as.y + h4.z * as.z + h4.w * as.w;
    float v2 = h4.x * ad.x + h4.y * ad.y + h4.z * ad.z + h4.w * ad.w;
    v1 += __shfl_down_sync(0xffffffffu, v1, 2, 4);
    v2 += __shfl_down_sync(0xffffffffu, v2, 2, 4);
    v1 += __shfl_down_sync(0xffffffffu, v1, 1, 4);
    v2 += __shfl_down_sync(0xffffffffu, v2, 1, 4);
    if ((lane & 3) == 0) {
        int head = lane >> 2;
        d_asrc[(size_t)g * NN * NH + n * NH + head] = v1;
        d_adst[(size_t)g * NN * NH + n * NH + head] = v2;
    }
}

// ================== combined launch kernels ===================================

__global__ void __launch_bounds__(1024) k_phaseA(const float* __restrict__ rel0,
                                                 const float* __restrict__ rel1) {
    int b = blockIdx.x;
    if (b < ZB) dev_zero(b);
    else        dev_normrel(b - ZB, rel0, rel1);
}

// gemm(graph0, layer0)  ||  hist
__global__ void __launch_bounds__(1024) k_phaseB(const float* __restrict__ ent0,
                                                 const float* __restrict__ W0,
                                                 const int* __restrict__ e0,
                                                 const int* __restrict__ e1) {
    __shared__ __align__(16) float smem[GGRP * DIMF * GNPB];
    int b = blockIdx.x;
    if (b < GB) dev_gemm_block(smem, b, 0, ent0, W0);
    else        dev_hist(b - GB, e0, e1);
}

// scan  ||  gemm(graph1, layer0)
__global__ void __launch_bounds__(1024) k_phaseC(const float* __restrict__ ent1,
                                                 const float* __restrict__ W0) {
    __shared__ __align__(16) float smem[GGRP * DIMF * GNPB];
    int b = blockIdx.x;
    if (b < 2) dev_scan(reinterpret_cast<int*>(smem), b);
    else       dev_gemm_block(smem, b - 2, 1, ent1, W0);
}

// scatter  ||  alpha(layer0)
__global__ void __launch_bounds__(1024) k_phaseD(const int* __restrict__ e0,
                                                 const int* __restrict__ e1,
                                                 const float* __restrict__ a_s,
                                                 const float* __restrict__ a_d) {
    int b = blockIdx.x;
    if (b < HB) dev_scatter(b, e0, e1);
    else        dev_alpha(b - HB, a_s, a_d);
}

// gemm(layer1) both graphs, reading d_x
__global__ void __launch_bounds__(1024) k_gemm_l1(const float* __restrict__ W1) {
    __shared__ __align__(16) float smem[GGRP * DIMF * GNPB];
    int b = blockIdx.x;
    int g = b >= GB;
    dev_gemm_block(smem, b - g * GB, g, d_x + (size_t)g * NN * DIMF, W1);
}

__global__ void __launch_bounds__(1024) k_alpha2(const float* __restrict__ a_s,
                                                 const float* __restrict__ a_d) {
    dev_alpha(blockIdx.x, a_s, a_d);
}

// ---- fused softmax-aggregate: warp per dst node, single pass, no atomics ----
__global__ void __launch_bounds__(256) k_agg(int last) {
    int gt = blockIdx.x * blockDim.x + threadIdx.x;
    int n = gt >> 5, lane = gt & 31;
    if (n >= NN) return;
    int g = blockIdx.y;
    const int* off = d_off + g * (NN + 1);
    const int* csrc = d_csrc + (size_t)g * EE;
    const float* hb = d_h + (size_t)g * NN * DIMF;
    const float* asb = d_asrc + (size_t)g * NN * NH;
    int head = lane >> 2;

    float adst_l = d_adst[(size_t)g * NN * NH + n * NH + head];

    int beg = off[n], end = off[n + 1];
    float4 acc = make_float4(0.f, 0.f, 0.f, 0.f);
    float den = 0.0f;

    int j = beg;
    for (; j + 4 <= end; j += 4) {
        int s0 = __ldg(&csrc[j]);
        int s1 = __ldg(&csrc[j + 1]);
        int s2 = __ldg(&csrc[j + 2]);
        int s3 = __ldg(&csrc[j + 3]);
        float al0 = __ldg(&asb[s0 * NH + head]);
        float al1 = __ldg(&asb[s1 * NH + head]);
        float al2 = __ldg(&asb[s2 * NH + head]);
        float al3 = __ldg(&asb[s3 * NH + head]);
        float4 h0 = reinterpret_cast<const float4*>(hb + (size_t)s0 * DIMF)[lane];
        float4 h1 = reinterpret_cast<const float4*>(hb + (size_t)s1 * DIMF)[lane];
        float4 h2 = reinterpret_cast<const float4*>(hb + (size_t)s2 * DIMF)[lane];
        float4 h3 = reinterpret_cast<const float4*>(hb + (size_t)s3 * DIMF)[lane];
        float v0 = al0 + adst_l; v0 = fmaxf(v0, 0.2f * v0);
        float v1 = al1 + adst_l; v1 = fmaxf(v1, 0.2f * v1);
        float v2 = al2 + adst_l; v2 = fmaxf(v2, 0.2f * v2);
        float v3 = al3 + adst_l; v3 = fmaxf(v3, 0.2f * v3);
        float w0 = __expf(v0);
        float w1 = __expf(v1);
        float w2 = __expf(v2);
        float w3 = __expf(v3);
        den += (w0 + w1) + (w2 + w3);
        acc.x = fmaf(w0, h0.x, fmaf(w1, h1.x, fmaf(w2, h2.x, fmaf(w3, h3.x, acc.x))));
        acc.y = fmaf(w0, h0.y, fmaf(w1, h1.y, fmaf(w2, h2.y, fmaf(w3, h3.y, acc.y))));
        acc.z = fmaf(w0, h0.z, fmaf(w1, h1.z, fmaf(w2, h2.z, fmaf(w3, h3.z, acc.z))));
        acc.w = fmaf(w0, h0.w, fmaf(w1, h1.w, fmaf(w2, h2.w, fmaf(w3, h3.w, acc.w))));
    }
    for (; j < end; j++) {
        int s0 = __ldg(&csrc[j]);
        float al0 = __ldg(&asb[s0 * NH + head]);
        float4 h0 = reinterpret_cast<const float4*>(hb + (size_t)s0 * DIMF)[lane];
        float v0 = al0 + adst_l; v0 = fmaxf(v0, 0.2f * v0);
        float w0 = __expf(v0);
        den += w0;
        acc.x = fmaf(w0, h0.x, acc.x);
        acc.y = fmaf(w0, h0.y, acc.y);
        acc.z = fmaf(w0, h0.z, acc.z);
        acc.w = fmaf(w0, h0.w, acc.w);
    }

    float inv = 1.0f / fmaxf(den, 1e-16f);
    acc.x *= inv; acc.y *= inv; acc.z *= inv; acc.w *= inv;

    if (last) {
        reinterpret_cast<float4*>(d_feat + (size_t)g * NN * DIMF +
                                  (size_t)n * DIMF)[lane] = acc;
        float s2 = acc.x * acc.x + acc.y * acc.y + acc.z * acc.z + acc.w * acc.w;
#pragma unroll
        for (int o = 16; o > 0; o >>= 1) s2 += __shfl_xor_sync(0xffffffffu, s2, o);
        float sc = 1.0f / fmaxf(sqrtf(s2), 1e-12f);
        uint2 bv = pack_bf16x4(acc.x * sc, acc.y * sc, acc.z * sc, acc.w * sc);
        reinterpret_cast<uint2*>(d_gnorm + (size_t)g * NN * DIMF +
                                 (size_t)n * DIMF)[lane] = bv;
    } else {
        acc.x = (acc.x > 0.f) ? acc.x : expm1f(acc.x);
        acc.y = (acc.y > 0.f) ? acc.y : expm1f(acc.y);
        acc.z = (acc.z > 0.f) ? acc.z : expm1f(acc.z);
        acc.w = (acc.w > 0.f) ? acc.w : expm1f(acc.w);
        reinterpret_cast<float4*>(d_x + (size_t)g * NN * DIMF +
                                  (size_t)n * DIMF)[lane] = acc;
    }
}

// ---- transE / rule over bf16 rows -------------------------------------------
__device__ __forceinline__ float transe_tv_warp(const __nv_bfloat16* gn,
                                                const __nv_bfloat16* rn,
                                                int hh, int tt, int rr, int lane) {
    uint2 au = reinterpret_cast<const uint2*>(gn + (size_t)hh * DIMF)[lane];
    uint2 bu = reinterpret_cast<const uint2*>(rn + (size_t)rr * DIMF)[lane];
    uint2 cu = reinterpret_cast<const uint2*>(gn + (size_t)tt * DIMF)[lane];
    float2 a0 = __bfloat1622float2(*reinterpret_cast<__nv_bfloat162*>(&au.x));
    float2 a1 = __bfloat1622float2(*reinterpret_cast<__nv_bfloat162*>(&au.y));
    float2 b0 = __bfloat1622float2(*reinterpret_cast<__nv_bfloat162*>(&bu.x));
    float2 b1 = __bfloat1622float2(*reinterpret_cast<__nv_bfloat162*>(&bu.y));
    float2 c0 = __bfloat1622float2(*reinterpret_cast<__nv_bfloat162*>(&cu.x));
    float2 c1 = __bfloat1622float2(*reinterpret_cast<__nv_bfloat162*>(&cu.y));
    float s = fabsf(a0.x + b0.x - c0.x) + fabsf(a0.y + b0.y - c0.y) +
              fabsf(a1.x + b1.x - c1.x) + fabsf(a1.y + b1.y - c1.y);
#pragma unroll
    for (int o = 16; o > 0; o >>= 1) s += __shfl_down_sync(0xffffffffu, s, o);
    return 1.0f - s * TV_INV;
}

__global__ void __launch_bounds__(256) k_transe(const int* __restrict__ h0,
                                                const int* __restrict__ h1,
                                                const int* __restrict__ t0,
                                                const int* __restrict__ t1,
                                                const int* __restrict__ r0,
                                                const int* __restrict__ r1,
                                                float* __restrict__ out) {
    int gt = blockIdx.x * blockDim.x + threadIdx.x;
    int w = gt >> 5, lane = gt & 31;
    if (w >= 2 * TT) return;
    int g = blockIdx.y;
    const int* hI = g ? h1 : h0;
    const int* tI = g ? t1 : t0;
    const int* rI = g ? r1 : r0;
    const __nv_bfloat16* gn = d_gnorm + (size_t)g * NN * DIMF;
    const __nv_bfloat16* rn = d_rnorm + (size_t)g * NRELC * DIMF;
    float tv = transe_tv_warp(gn, rn, hI[w], tI[w], rI[w], lane);
    if (lane == 0) out[(size_t)g * 2 * TT + w] = tv;
}

__global__ void __launch_bounds__(256) k_rule(const int* __restrict__ rh0,
                                              const int* __restrict__ rh1,
                                              const int* __restrict__ rt0,
                                              const int* __restrict__ rt1,
                                              const int* __restrict__ rr0,
                                              const int* __restrict__ rr1,
                                              const int* __restrict__ pm0,
                                              const int* __restrict__ pm1,
                                              const float* __restrict__ tvbase,
                                              float* __restrict__ out) {
    int gt = blockIdx.x * blockDim.x + threadIdx.x;
    int w = gt >> 5, lane = gt & 31;
    if (w >= RRULE) return;
    int g = blockIdx.y;
    const int* rh = g ? rh1 : rh0;
    const int* rt = g ? rt1 : rt0;
    const int* rr = g ? rr1 : rr0;
    const int* prem = g ? pm1 : pm0;
    const __nv_bfloat16* gn = d_gnorm + (size_t)g * NN * DIMF;
    const __nv_bfloat16* rn = d_rnorm + (size_t)g * NRELC * DIMF;
    const float* tv = tvbase + (size_t)g * 2 * TT;
    float rs = transe_tv_warp(gn, rn, rh[w], rt[w], rr[w], lane);
    if (lane == 0) {
        int p0 = prem[w * 2 + 0];
        int p1 = prem[w * 2 + 1];
        float f1 = (p0 < TT) ? tv[p0 * 2 + g] : 1.0f;
        float f2 = (p1 < TT) ? tv[p1 * 2 + g] : 1.0f;
        out[(size_t)g * RRULE + w] = 1.0f + f1 * f2 * (rs - 1.0f);
    }
}

__global__ void k_gather(const int* __restrict__ i0, const int* __restrict__ i1,
                         float* __restrict__ out) {
    int i = blockIdx.x * blockDim.x + threadIdx.x;
    if (i >= BB * DIMF) return;
    int g = blockIdx.y;
    const int* idx = g ? i1 : i0;
    int b = i >> 7, c = i & 127;
    out[(size_t)g * BB * DIMF + i] =
        d_feat[(size_t)g * NN * DIMF + (size_t)idx[b] * DIMF + c];
}

// ---------------- host orchestration ------------------------------------------
static inline int nblk(long n, int t) { return (int)((n + t - 1) / t); }

extern "C" void kernel_launch(void* const* d_in, const int* in_sizes, int n_in,
                              void* d_out, int out_size) {
    const float* ent0 = (const float*)d_in[0];
    const float* ent1 = (const float*)d_in[1];
    const float* rel0 = (const float*)d_in[2];
    const float* rel1 = (const float*)d_in[3];
    const float* W    = (const float*)d_in[4];
    const float* a_s  = (const float*)d_in[5];
    const float* a_d  = (const float*)d_in[6];
    const int* dat0 = (const int*)d_in[7];
    const int* dat1 = (const int*)d_in[8];
    const int* edg0 = (const int*)d_in[9];
    const int* edg1 = (const int*)d_in[10];
    const int* h0 = (const int*)d_in[11];
    const int* t0 = (const int*)d_in[12];
    const int* r0 = (const int*)d_in[13];
    const int* h1 = (const int*)d_in[14];
    const int* t1 = (const int*)d_in[15];
    const int* r1 = (const int*)d_in[16];
    const int* rh0 = (const int*)d_in[17];
    const int* rt0 = (const int*)d_in[18];
    const int* rr0 = (const int*)d_in[19];
    const int* pm0 = (const int*)d_in[20];
    const int* rh1 = (const int*)d_in[21];
    const int* rt1 = (const int*)d_in[22];
    const int* rr1 = (const int*)d_in[23];
    const int* pm1 = (const int*)d_in[24];

    float* out      = (float*)d_out;
    float* out_feat = out;
    float* out_tv   = out + 2 * (size_t)BB * DIMF;
    float* out_rule = out_tv + 4 * (size_t)TT;

    const float* W0 = W;
    const float* W1 = W + (size_t)DIMF * DIMF;

    // phase A: zero counters || l2-normalize relations
    k_phaseA<<<ZB + RB, 1024>>>(rel0, rel1);
    // phase B: gemm(g0, l0) || histogram
    k_phaseB<<<GB + HB, 1024>>>(ent0, W0, edg0, edg1);
    // phase C: scan || gemm(g1, l0)
    k_phaseC<<<2 + GB, 1024>>>(ent1, W0);
    // phase D: scatter || alpha(l0)
    k_phaseD<<<HB + AB, 1024>>>(edg0, edg1, a_s, a_d);
    // layer 0 aggregate
    k_agg<<<dim3(nblk((long)NN * 32, 256), 2), 256>>>(0);
    // layer 1
    k_gemm_l1<<<2 * GB, 1024>>>(W1);
    k_alpha2<<<AB, 1024>>>(a_s + DIMF, a_d + DIMF);
    k_agg<<<dim3(nblk((long)NN * 32, 256), 2), 256>>>(1);
    // heads
    k_transe<<<dim3(nblk((long)2 * TT * 32, 256), 2), 256>>>(h0, h1, t0, t1, r0, r1, out_tv);
    k_rule<<<dim3(nblk((long)RRULE * 32, 256), 2), 256>>>(rh0, rh1, rt0, rt1, rr0, rr1,
                                                          pm0, pm1, out_tv, out_rule);
    k_gather<<<dim3(nblk((long)BB * DIMF, 256), 2), 256>>>(dat0, dat1, out_feat);

    (void)in_sizes; (void)n_in; (void)out_size;
}

// round 7
// speedup vs baseline: 1.0159x; 1.0018x over previous
#include <cuda_runtime.h>
#include <cuda_bf16.h>
#include <math.h>

#define NN    50000
#define DIMF  128
#define NH    8
#define EE    800000
#define NRELC 2000
#define TT    200000
#define RRULE 50000
#define BB    10000
#define TV_INV 0.029462782549439483f   // 1/(3*sqrt(128))

// gemm tiling: 8 groups of 128 threads, 8 nodes per group -> 64 nodes/block
#define GNPB   8
#define GGRP   8
#define GNODES (GNPB * GGRP)
#define GB     ((NN + GNODES - 1) / GNODES)       // 782 gemm blocks per graph
#define ZB     ((2 * NN + 1023) / 1024)           // 98
#define RB     ((2 * NRELC + 31) / 32)            // 125
#define HB     ((2 * EE + 1023) / 1024)           // 1563
#define AB     ((2 * NN + 31) / 32)               // 3125

// ---------------- device scratch ---------------------------------------------
__device__ __align__(16) float d_x[2 * NN * DIMF];
__device__ __align__(16) float d_h[2 * NN * DIMF];
__device__ float               d_asrc[2 * NN * NH];
__device__ float               d_adst[2 * NN * NH];
__device__ __align__(16) float d_feat[2 * NN * DIMF];
__device__ __align__(16) __nv_bfloat16 d_gnorm[2 * NN * DIMF];
__device__ __align__(16) __nv_bfloat16 d_rnorm[2 * NRELC * DIMF];
__device__ int d_cnt[2 * NN];
__device__ int d_off[2 * (NN + 1)];
__device__ int d_cur[2 * NN];
__device__ int d_csrc[2 * EE];

// ---------------- packed helpers ----------------------------------------------
__device__ __forceinline__ unsigned long long pack2(float x, float y) {
    unsigned long long r;
    asm("mov.b64 %0, {%1, %2};" : "=l"(r) : "f"(x), "f"(y));
    return r;
}
__device__ __forceinline__ void unpack2(unsigned long long v, float& x, float& y) {
    asm("mov.b64 {%0, %1}, %2;" : "=f"(x), "=f"(y) : "l"(v));
}
__device__ __forceinline__ unsigned long long fma2(unsigned long long a,
                                                   unsigned long long b,
                                                   unsigned long long c) {
    unsigned long long r;
    asm("fma.rn.f32x2 %0, %1, %2, %3;" : "=l"(r) : "l"(a), "l"(b), "l"(c));
    return r;
}
__device__ __forceinline__ uint2 pack_bf16x4(float a, float b, float c, float d) {
    __nv_bfloat162 p0 = __floats2bfloat162_rn(a, b);
    __nv_bfloat162 p1 = __floats2bfloat162_rn(c, d);
    uint2 u;
    u.x = *reinterpret_cast<unsigned int*>(&p0);
    u.y = *reinterpret_cast<unsigned int*>(&p1);
    return u;
}

// ================== device building blocks =====================================

__device__ __forceinline__ void dev_zero(int b) {
    int i = b * 1024 + threadIdx.x;
    if (i < 2 * NN) d_cnt[i] = 0;
}

__device__ __forceinline__ void dev_normrel(int b, const float* __restrict__ rel0,
                                            const float* __restrict__ rel1) {
    int wid = threadIdx.x >> 5, lane = threadIdx.x & 31;
    int row = b * 32 + wid;
    if (row >= 2 * NRELC) return;
    int g = row >= NRELC;
    int r = row - g * NRELC;
    const float* rel = g ? rel1 : rel0;
    float4 v = reinterpret_cast<const float4*>(rel + (size_t)r * DIMF)[lane];
    float s = v.x * v.x + v.y * v.y + v.z * v.z + v.w * v.w;
#pragma unroll
    for (int o = 16; o > 0; o >>= 1) s += __shfl_xor_sync(0xffffffffu, s, o);
    float sc = 1.0f / fmaxf(sqrtf(s), 1e-12f);
    uint2 bv = pack_bf16x4(v.x * sc, v.y * sc, v.z * sc, v.w * sc);
    reinterpret_cast<uint2*>(d_rnorm + (size_t)g * NRELC * DIMF +
                             (size_t)r * DIMF)[lane] = bv;
}

__device__ __forceinline__ void dev_hist(int b, const int* __restrict__ e0,
                                         const int* __restrict__ e1) {
    int idx = b * 1024 + threadIdx.x;
    if (idx >= 2 * EE) return;
    int g = idx >= EE;
    int e = idx - g * EE;
    const int* edg = g ? e1 : e0;
    atomicAdd(&d_cnt[g * NN + edg[EE + e]], 1);
}

__device__ __forceinline__ void dev_scatter(int b, const int* __restrict__ e0,
                                            const int* __restrict__ e1) {
    int idx = b * 1024 + threadIdx.x;
    if (idx >= 2 * EE) return;
    int g = idx >= EE;
    int e = idx - g * EE;
    const int* edg = g ? e1 : e0;
    int s = edg[e];
    int d = edg[EE + e];
    int p = atomicAdd(&d_cur[g * NN + d], 1);
    d_csrc[(size_t)g * EE + p] = s;
}

// block-wide prefix scan of d_cnt[g] -> d_off/d_cur, prefetched chunk loop
__device__ __forceinline__ void dev_scan(int* wsum, int g) {
    int t = threadIdx.x;
    int lane = t & 31, wid = t >> 5;
    const int NCH = (NN + 1023) / 1024;
    int run = 0;
    int val = (t < NN) ? d_cnt[g * NN + t] : 0;
    for (int c = 0; c < NCH; c++) {
        int inext = (c + 1) * 1024 + t;
        int vnext = (c + 1 < NCH && inext < NN) ? d_cnt[g * NN + inext] : 0;
        int incl = val;
#pragma unroll
        for (int o = 1; o < 32; o <<= 1) {
            int u = __shfl_up_sync(0xffffffffu, incl, o);
            if (lane >= o) incl += u;
        }
        if (lane == 31) wsum[wid] = incl;
        __syncthreads();
        if (wid == 0) {
            int ws = wsum[lane];
#pragma unroll
            for (int o = 1; o < 32; o <<= 1) {
                int u = __shfl_up_sync(0xffffffffu, ws, o);
                if (lane >= o) ws += u;
            }
            wsum[lane] = ws;
        }
        __syncthreads();
        int wb = (wid > 0) ? wsum[wid - 1] : 0;
        int i = c * 1024 + t;
        int excl = run + wb + incl - val;
        if (i < NN) {
            d_off[g * (NN + 1) + i] = excl;
            d_cur[g * NN + i] = excl;
        }
        run += wsum[31];
        __syncthreads();
        val = vnext;
    }
    if (t == 0) d_off[g * (NN + 1) + NN] = EE;
}

// gemm block: 8 groups x 128 threads, each group does 8 nodes
__device__ __forceinline__ void dev_gemm_block(float* smem, int nodeblk, int g,
                                               const float* __restrict__ xsrc,
                                               const float* __restrict__ W) {
    int t = threadIdx.x;
    int grp = t >> 7, lt = t & 127;
    float* xst = smem + grp * (DIMF * GNPB);   // [d][u]: d*8+u
    int nb = nodeblk * GNODES + grp * GNPB;

    for (int k = lt; k < GNPB * DIMF; k += 128) {
        int u = k >> 7, d = k & 127;
        int n = nb + u;
        xst[d * GNPB + u] = (n < NN) ? xsrc[(size_t)n * DIMF + d] : 0.0f;
    }
    __syncthreads();

    unsigned long long a0 = 0, a1 = 0, a2 = 0, a3 = 0;
#pragma unroll 4
    for (int d = 0; d < DIMF; d++) {
        float w = __ldg(W + d * DIMF + lt);
        unsigned long long w2 = pack2(w, w);
        const ulonglong2* xr = reinterpret_cast<const ulonglong2*>(xst + d * GNPB);
        ulonglong2 p0 = xr[0];
        ulonglong2 p1 = xr[1];
        a0 = fma2(p0.x, w2, a0);
        a1 = fma2(p0.y, w2, a1);
        a2 = fma2(p1.x, w2, a2);
        a3 = fma2(p1.y, w2, a3);
    }
    float v[GNPB];
    unpack2(a0, v[0], v[1]);
    unpack2(a1, v[2], v[3]);
    unpack2(a2, v[4], v[5]);
    unpack2(a3, v[6], v[7]);
    float* hb = d_h + (size_t)g * NN * DIMF;
#pragma unroll
    for (int u = 0; u < GNPB; u++) {
        int n = nb + u;
        if (n < NN) hb[(size_t)n * DIMF + lt] = v[u];
    }
}

// warp per node, flattened over both graphs
__device__ __forceinline__ void dev_alpha(int b, const float* __restrict__ a_s,
                                          const float* __restrict__ a_d) {
    int wid = threadIdx.x >> 5, lane = threadIdx.x & 31;
    int nf = b * 32 + wid;
    if (nf >= 2 * NN) return;
    int g = nf >= NN;
    int n = nf - g * NN;
    const float* hb = d_h + (size_t)g * NN * DIMF;
    float4 h4 = reinterpret_cast<const float4*>(hb + (size_t)n * DIMF)[lane];
    float4 as = reinterpret_cast<const float4*>(a_s)[lane];
    float4 ad = reinterpret_cast<const float4*>(a_d)[lane];
    float v1 = h4.x * as.x + h4.y * as.y + h4.z * as.z + h4.w * as.w;
    float v2 = h4.x * ad.x + h4.y * ad.y + h4.z * ad.z + h4.w * ad.w;
    v1 += __shfl_down_sync(0xffffffffu, v1, 2, 4);
    v2 += __shfl_down_sync(0xffffffffu, v2, 2, 4);
    v1 += __shfl_down_sync(0xffffffffu, v1, 1, 4);
    v2 += __shfl_down_sync(0xffffffffu, v2, 1, 4);
    if ((lane & 3) == 0) {
        int head = lane >> 2;
        d_asrc[(size_t)g * NN * NH + n * NH + head] = v1;
        d_adst[(size_t)g * NN * NH + n * NH + head] = v2;
    }
}

// ================== combined launch kernels ===================================

__global__ void __launch_bounds__(1024) k_phaseA(const float* __restrict__ rel0,
                                                 const float* __restrict__ rel1) {
    int b = blockIdx.x;
    if (b < ZB) dev_zero(b);
    else        dev_normrel(b - ZB, rel0, rel1);
}

// gemm(graph0, layer0)  ||  hist
__global__ void __launch_bounds__(1024) k_phaseB(const float* __restrict__ ent0,
                                                 const float* __restrict__ W0,
                                                 const int* __restrict__ e0,
                                                 const int* __restrict__ e1) {
    __shared__ __align__(16) float smem[GGRP * DIMF * GNPB];
    int b = blockIdx.x;
    if (b < GB) dev_gemm_block(smem, b, 0, ent0, W0);
    else        dev_hist(b - GB, e0, e1);
}

// scan  ||  gemm(graph1, layer0)
__global__ void __launch_bounds__(1024) k_phaseC(const float* __restrict__ ent1,
                                                 const float* __restrict__ W0) {
    __shared__ __align__(16) float smem[GGRP * DIMF * GNPB];
    int b = blockIdx.x;
    if (b < 2) dev_scan(reinterpret_cast<int*>(smem), b);
    else       dev_gemm_block(smem, b - 2, 1, ent1, W0);
}

// scatter  ||  alpha(layer0)
__global__ void __launch_bounds__(1024) k_phaseD(const int* __restrict__ e0,
                                                 const int* __restrict__ e1,
                                                 const float* __restrict__ a_s,
                                                 const float* __restrict__ a_d) {
    int b = blockIdx.x;
    if (b < HB) dev_scatter(b, e0, e1);
    else        dev_alpha(b - HB, a_s, a_d);
}

// gemm(layer1) both graphs, reading d_x
__global__ void __launch_bounds__(1024) k_gemm_l1(const float* __restrict__ W1) {
    __shared__ __align__(16) float smem[GGRP * DIMF * GNPB];
    int b = blockIdx.x;
    int g = b >= GB;
    dev_gemm_block(smem, b - g * GB, g, d_x + (size_t)g * NN * DIMF, W1);
}

__global__ void __launch_bounds__(1024) k_alpha2(const float* __restrict__ a_s,
                                                 const float* __restrict__ a_d) {
    dev_alpha(blockIdx.x, a_s, a_d);
}

// ---- fused softmax-aggregate: warp per dst node ------------------------------
// chunk-of-32 coalesced csrc load; weight phase computes 4 edges x 8 heads per
// warp (1 alpha load + 1 exp per lane covers 4 edges); fma phase issues the 4
// 512B h-row gathers before consuming weights.
__global__ void __launch_bounds__(256) k_agg(int last) {
    int gt = blockIdx.x * blockDim.x + threadIdx.x;
    int n = gt >> 5, lane = gt & 31;
    if (n >= NN) return;
    int g = blockIdx.y;
    const int* off = d_off + g * (NN + 1);
    const int* csrc = d_csrc + (size_t)g * EE;
    const float* hb = d_h + (size_t)g * NN * DIMF;
    const float* asb = d_asrc + (size_t)g * NN * NH;

    int head_acc = lane >> 2;     // head owning this lane's float4 channels
    int head_w   = lane & 7;      // head this lane computes weights for
    float adst_w = d_adst[(size_t)g * NN * NH + n * NH + head_w];

    int beg = off[n], end = off[n + 1];
    float4 acc = make_float4(0.f, 0.f, 0.f, 0.f);
    float den_l = 0.0f;

    int j = beg;
    while (j < end) {
        int cnt = end - j;
        if (cnt > 32) cnt = 32;
        int idx = j + ((lane < cnt) ? lane : (cnt - 1));
        int sv = __ldg(&csrc[idx]);              // 32 edge srcs, coalesced

        for (int e0 = 0; e0 < cnt; e0 += 4) {
            int m = cnt - e0;
            if (m > 4) m = 4;
            // ---- weight phase: lane = (edge eo, head head_w) ----
            int eo = lane >> 3;
            int epos = e0 + eo;
            int esrc = (epos < cnt) ? epos : (cnt - 1);
            int se_w = __shfl_sync(0xffffffffu, sv, esrc);
            float al = __ldg(&asb[se_w * NH + head_w]);
            float v = al + adst_w;
            v = fmaxf(v, 0.2f * v);
            float w = (epos < cnt) ? __expf(v) : 0.0f;
            den_l += w;
            // ---- fma phase: issue h loads first, then consume weights ----
            float4 hv[4];
            int ss[4];
#pragma unroll
            for (int e = 0; e < 4; e++) {
                if (e >= m) break;
                ss[e] = __shfl_sync(0xffffffffu, sv, e0 + e);
                hv[e] = reinterpret_cast<const float4*>(hb + (size_t)ss[e] * DIMF)[lane];
            }
#pragma unroll
            for (int e = 0; e < 4; e++) {
                if (e >= m) break;
                float wb = __shfl_sync(0xffffffffu, w, (e << 3) + head_acc);
                acc.x = fmaf(wb, hv[e].x, acc.x);
                acc.y = fmaf(wb, hv[e].y, acc.y);
                acc.z = fmaf(wb, hv[e].z, acc.z);
                acc.w = fmaf(wb, hv[e].w, acc.w);
            }
        }
        j += cnt;
    }

    // reduce den over the 4 lanes sharing head_w (strides 8, 16)
    den_l += __shfl_xor_sync(0xffffffffu, den_l, 8);
    den_l += __shfl_xor_sync(0xffffffffu, den_l, 16);
    float den = __shfl_sync(0xffffffffu, den_l, head_acc);  // lane h<8 has head_w==h

    float inv = 1.0f / fmaxf(den, 1e-16f);
    acc.x *= inv; acc.y *= inv; acc.z *= inv; acc.w *= inv;

    if (last) {
        reinterpret_cast<float4*>(d_feat + (size_t)g * NN * DIMF +
                                  (size_t)n * DIMF)[lane] = acc;
        float s2 = acc.x * acc.x + acc.y * acc.y + acc.z * acc.z + acc.w * acc.w;
#pragma unroll
        for (int o = 16; o > 0; o >>= 1) s2 += __shfl_xor_sync(0xffffffffu, s2, o);
        float sc = 1.0f / fmaxf(sqrtf(s2), 1e-12f);
        uint2 bv = pack_bf16x4(acc.x * sc, acc.y * sc, acc.z * sc, acc.w * sc);
        reinterpret_cast<uint2*>(d_gnorm + (size_t)g * NN * DIMF +
                                 (size_t)n * DIMF)[lane] = bv;
    } else {
        acc.x = (acc.x > 0.f) ? acc.x : expm1f(acc.x);
        acc.y = (acc.y > 0.f) ? acc.y : expm1f(acc.y);
        acc.z = (acc.z > 0.f) ? acc.z : expm1f(acc.z);
        acc.w = (acc.w > 0.f) ? acc.w : expm1f(acc.w);
        reinterpret_cast<float4*>(d_x + (size_t)g * NN * DIMF +
                                  (size_t)n * DIMF)[lane] = acc;
    }
}

// ---- transE / rule: 4 triples per warp, 8 lanes per triple -------------------
__device__ __forceinline__ float ad2(unsigned int a, unsigned int b, unsigned int c) {
    float2 fa = __bfloat1622float2(*reinterpret_cast<__nv_bfloat162*>(&a));
    float2 fb = __bfloat1622float2(*reinterpret_cast<__nv_bfloat162*>(&b));
    float2 fc = __bfloat1622float2(*reinterpret_cast<__nv_bfloat162*>(&c));
    return fabsf(fa.x + fb.x - fc.x) + fabsf(fa.y + fb.y - fc.y);
}
__device__ __forceinline__ float ad8(uint4 a, uint4 b, uint4 c) {
    return ad2(a.x, b.x, c.x) + ad2(a.y, b.y, c.y) +
           ad2(a.z, b.z, c.z) + ad2(a.w, b.w, c.w);
}

// returns tv for this 8-lane group's triple (all 8 lanes get it)
__device__ __forceinline__ float tv8(const __nv_bfloat16* gn,
                                     const __nv_bfloat16* rn,
                                     int hh, int tt, int rr, int lq) {
    const uint4* pa = reinterpret_cast<const uint4*>(gn + (size_t)hh * DIMF);
    const uint4* pb = reinterpret_cast<const uint4*>(rn + (size_t)rr * DIMF);
    const uint4* pc = reinterpret_cast<const uint4*>(gn + (size_t)tt * DIMF);
    uint4 a0 = pa[2 * lq], a1 = pa[2 * lq + 1];
    uint4 b0 = pb[2 * lq], b1 = pb[2 * lq + 1];
    uint4 c0 = pc[2 * lq], c1 = pc[2 * lq + 1];
    float s = ad8(a0, b0, c0) + ad8(a1, b1, c1);
    s += __shfl_xor_sync(0xffffffffu, s, 1);
    s += __shfl_xor_sync(0xffffffffu, s, 2);
    s += __shfl_xor_sync(0xffffffffu, s, 4);
    return 1.0f - s * TV_INV;
}

__global__ void __launch_bounds__(256) k_transe(const int* __restrict__ h0,
                                                const int* __restrict__ h1,
                                                const int* __restrict__ t0,
                                                const int* __restrict__ t1,
                                                const int* __restrict__ r0,
                                                const int* __restrict__ r1,
                                                float* __restrict__ out) {
    int gt = blockIdx.x * blockDim.x + threadIdx.x;
    int warp = gt >> 5, lane = gt & 31;
    int sub = lane >> 3, lq = lane & 7;
    int w4 = warp * 4 + sub;                 // 2*TT = 400000 divisible by 4
    if (w4 >= 2 * TT) return;                // whole-warp uniform (exact fit)
    int g = blockIdx.y;
    const int* hI = g ? h1 : h0;
    const int* tI = g ? t1 : t0;
    const int* rI = g ? r1 : r0;
    const __nv_bfloat16* gn = d_gnorm + (size_t)g * NN * DIMF;
    const __nv_bfloat16* rn = d_rnorm + (size_t)g * NRELC * DIMF;
    float tv = tv8(gn, rn, hI[w4], tI[w4], rI[w4], lq);
    if (lq == 0) out[(size_t)g * 2 * TT + w4] = tv;
}

__global__ void __launch_bounds__(256) k_rule(const int* __restrict__ rh0,
                                              const int* __restrict__ rh1,
                                              const int* __restrict__ rt0,
                                              const int* __restrict__ rt1,
                                              const int* __restrict__ rr0,
                                              const int* __restrict__ rr1,
                                              const int* __restrict__ pm0,
                                              const int* __restrict__ pm1,
                                              const float* __restrict__ tvbase,
                                              float* __restrict__ out) {
    int gt = blockIdx.x * blockDim.x + threadIdx.x;
    int warp = gt >> 5, lane = gt & 31;
    if (warp * 4 >= RRULE) return;           // RRULE divisible by 4: whole-warp
    int sub = lane >> 3, lq = lane & 7;
    int w4 = warp * 4 + sub;
    int g = blockIdx.y;
    const int* rh = g ? rh1 : rh0;
    const int* rt = g ? rt1 : rt0;
    const int* rr = g ? rr1 : rr0;
    const int* prem = g ? pm1 : pm0;
    const __nv_bfloat16* gn = d_gnorm + (size_t)g * NN * DIMF;
    const __nv_bfloat16* rn = d_rnorm + (size_t)g * NRELC * DIMF;
    const float* tv = tvbase + (size_t)g * 2 * TT;
    float rs = tv8(gn, rn, rh[w4], rt[w4], rr[w4], lq);
    if (lq == 0) {
        int p0 = prem[w4 * 2 + 0];
        int p1 = prem[w4 * 2 + 1];
        float f1 = (p0 < TT) ? tv[p0 * 2 + g] : 1.0f;
        float f2 = (p1 < TT) ? tv[p1 * 2 + g] : 1.0f;
        out[(size_t)g * RRULE + w4] = 1.0f + f1 * f2 * (rs - 1.0f);
    }
}

__global__ void k_gather(const int* __restrict__ i0, const int* __restrict__ i1,
                         float* __restrict__ out) {
    int i = blockIdx.x * blockDim.x + threadIdx.x;
    if (i >= BB * DIMF) return;
    int g = blockIdx.y;
    const int* idx = g ? i1 : i0;
    int b = i >> 7, c = i & 127;
    out[(size_t)g * BB * DIMF + i] =
        d_feat[(size_t)g * NN * DIMF + (size_t)idx[b] * DIMF + c];
}

// ---------------- host orchestration ------------------------------------------
static inline int nblk(long n, int t) { return (int)((n + t - 1) / t); }

extern "C" void kernel_launch(void* const* d_in, const int* in_sizes, int n_in,
                              void* d_out, int out_size) {
    const float* ent0 = (const float*)d_in[0];
    const float* ent1 = (const float*)d_in[1];
    const float* rel0 = (const float*)d_in[2];
    const float* rel1 = (const float*)d_in[3];
    const float* W    = (const float*)d_in[4];
    const float* a_s  = (const float*)d_in[5];
    const float* a_d  = (const float*)d_in[6];
    const int* dat0 = (const int*)d_in[7];
    const int* dat1 = (const int*)d_in[8];
    const int* edg0 = (const int*)d_in[9];
    const int* edg1 = (const int*)d_in[10];
    const int* h0 = (const int*)d_in[11];
    const int* t0 = (const int*)d_in[12];
    const int* r0 = (const int*)d_in[13];
    const int* h1 = (const int*)d_in[14];
    const int* t1 = (const int*)d_in[15];
    const int* r1 = (const int*)d_in[16];
    const int* rh0 = (const int*)d_in[17];
    const int* rt0 = (const int*)d_in[18];
    const int* rr0 = (const int*)d_in[19];
    const int* pm0 = (const int*)d_in[20];
    const int* rh1 = (const int*)d_in[21];
    const int* rt1 = (const int*)d_in[22];
    const int* rr1 = (const int*)d_in[23];
    const int* pm1 = (const int*)d_in[24];

    float* out      = (float*)d_out;
    float* out_feat = out;
    float* out_tv   = out + 2 * (size_t)BB * DIMF;
    float* out_rule = out_tv + 4 * (size_t)TT;

    const float* W0 = W;
    const float* W1 = W + (size_t)DIMF * DIMF;

    // phase A: zero counters || l2-normalize relations
    k_phaseA<<<ZB + RB, 1024>>>(rel0, rel1);
    // phase B: gemm(g0, l0) || histogram
    k_phaseB<<<GB + HB, 1024>>>(ent0, W0, edg0, edg1);
    // phase C: scan || gemm(g1, l0)
    k_phaseC<<<2 + GB, 1024>>>(ent1, W0);
    // phase D: scatter || alpha(l0)
    k_phaseD<<<HB + AB, 1024>>>(edg0, edg1, a_s, a_d);
    // layer 0 aggregate
    k_agg<<<dim3(nblk((long)NN * 32, 256), 2), 256>>>(0);
    // layer 1
    k_gemm_l1<<<2 * GB, 1024>>>(W1);
    k_alpha2<<<AB, 1024>>>(a_s + DIMF, a_d + DIMF);
    k_agg<<<dim3(nblk((long)NN * 32, 256), 2), 256>>>(1);
    // heads: 4 triples per warp
    k_transe<<<dim3(nblk((long)(2 * TT / 4) * 32, 256), 2), 256>>>(h0, h1, t0, t1,
                                                                   r0, r1, out_tv);
    k_rule<<<dim3(nblk((long)(RRULE / 4) * 32, 256), 2), 256>>>(rh0, rh1, rt0, rt1,
                                                                rr0, rr1, pm0, pm1,
                                                                out_tv, out_rule);
    k_gather<<<dim3(nblk((long)BB * DIMF, 256), 2), 256>>>(dat0, dat1, out_feat);

    (void)in_sizes; (void)n_in; (void)out_size;
}